// round 5
// baseline (speedup 1.0000x reference)
#include <cuda_runtime.h>
#include <math.h>

// x: (16, 10, 512, 512) f32. out: (16, 8, 512, 512) f32.
// Per pixel: mag = sqrt(x[8]^2 + x[9]^2); k = argmax over x[0..7] (first max);
// out[c] = (c==k) ? mag : 0.
//
// One thread per float4. Channel stride = 65536 float4s; all accesses 16B
// coalesced. Reads use __ldcs (evict-first: zero reuse) to reserve L2
// capacity for the write stream, so dirty output lines accumulate and flush
// in large sequential bursts. Stores use default policy (evict-normal).

#define VPB 65536            // float4 vectors per channel (512*512/4)
#define NBATCH 16
#define TOTAL_VEC (NBATCH * VPB)   // 1,048,576 threads exactly

__global__ __launch_bounds__(256, 4) void histogram_layer_kernel(
    const float4* __restrict__ x, float4* __restrict__ out)
{
    int i = blockIdx.x * blockDim.x + threadIdx.x;  // grid exact, no guard

    int b = i >> 16;          // i / VPB
    int p = i & (VPB - 1);    // i % VPB

    const float4* in_base = x + (size_t)b * 10 * VPB + p;

    // Front-batch ALL ten loads, streaming (evict-first in L2).
    float4 c0 = __ldcs(&in_base[(size_t)0 * VPB]);
    float4 c1 = __ldcs(&in_base[(size_t)1 * VPB]);
    float4 c2 = __ldcs(&in_base[(size_t)2 * VPB]);
    float4 c3 = __ldcs(&in_base[(size_t)3 * VPB]);
    float4 c4 = __ldcs(&in_base[(size_t)4 * VPB]);
    float4 c5 = __ldcs(&in_base[(size_t)5 * VPB]);
    float4 c6 = __ldcs(&in_base[(size_t)6 * VPB]);
    float4 c7 = __ldcs(&in_base[(size_t)7 * VPB]);
    float4 g0 = __ldcs(&in_base[(size_t)8 * VPB]);
    float4 g1 = __ldcs(&in_base[(size_t)9 * VPB]);

    // Per-lane argmax (strict > keeps lowest index on ties, like jnp.argmax)
    float4 cs[8] = {c0, c1, c2, c3, c4, c5, c6, c7};
    float bx = cs[0].x, by = cs[0].y, bz = cs[0].z, bw = cs[0].w;
    int ix = 0, iy = 0, iz = 0, iw = 0;
#pragma unroll
    for (int k = 1; k < 8; k++) {
        if (cs[k].x > bx) { bx = cs[k].x; ix = k; }
        if (cs[k].y > by) { by = cs[k].y; iy = k; }
        if (cs[k].z > bz) { bz = cs[k].z; iz = k; }
        if (cs[k].w > bw) { bw = cs[k].w; iw = k; }
    }

    float mx = sqrtf(g0.x * g0.x + g1.x * g1.x);
    float my = sqrtf(g0.y * g0.y + g1.y * g1.y);
    float mz = sqrtf(g0.z * g0.z + g1.z * g1.z);
    float mw = sqrtf(g0.w * g0.w + g1.w * g1.w);

    float4* out_base = out + (size_t)b * 8 * VPB + p;
#pragma unroll
    for (int k = 0; k < 8; k++) {
        float4 o;
        o.x = (ix == k) ? mx : 0.0f;
        o.y = (iy == k) ? my : 0.0f;
        o.z = (iz == k) ? mz : 0.0f;
        o.w = (iw == k) ? mw : 0.0f;
        out_base[(size_t)k * VPB] = o;  // default (evict-normal) stores
    }
}

extern "C" void kernel_launch(void* const* d_in, const int* in_sizes, int n_in,
                              void* d_out, int out_size)
{
    const float4* x = (const float4*)d_in[0];
    float4* out = (float4*)d_out;
    histogram_layer_kernel<<<TOTAL_VEC / 256, 256>>>(x, out);
}

// round 6
// speedup vs baseline: 1.0233x; 1.0233x over previous
#include <cuda_runtime.h>
#include <math.h>

// x: (16, 10, 512, 512) f32. out: (16, 8, 512, 512) f32.
// Per pixel: mag = sqrt(x[8]^2 + x[9]^2); k = argmax over x[0..7] (first max);
// out[c] = (c==k) ? mag : 0.
//
// One thread per float4. Channel stride = 65536 float4s; all accesses 16B
// coalesced. Stores are write-through (__stwt): no L2 dirty accumulation,
// writes stream to DRAM in issue order as full-sector bursts.

#define VPB 65536            // float4 vectors per channel (512*512/4)
#define NBATCH 16
#define TOTAL_VEC (NBATCH * VPB)   // 1,048,576 threads exactly

__global__ __launch_bounds__(256, 4) void histogram_layer_kernel(
    const float4* __restrict__ x, float4* __restrict__ out)
{
    int i = blockIdx.x * blockDim.x + threadIdx.x;  // grid exact, no guard

    int b = i >> 16;          // i / VPB
    int p = i & (VPB - 1);    // i % VPB

    const float4* in_base = x + (size_t)b * 10 * VPB + p;

    // Front-batch ALL ten loads into live registers before any consumption.
    float4 c0 = in_base[(size_t)0 * VPB];
    float4 c1 = in_base[(size_t)1 * VPB];
    float4 c2 = in_base[(size_t)2 * VPB];
    float4 c3 = in_base[(size_t)3 * VPB];
    float4 c4 = in_base[(size_t)4 * VPB];
    float4 c5 = in_base[(size_t)5 * VPB];
    float4 c6 = in_base[(size_t)6 * VPB];
    float4 c7 = in_base[(size_t)7 * VPB];
    float4 g0 = in_base[(size_t)8 * VPB];
    float4 g1 = in_base[(size_t)9 * VPB];

    // Per-lane argmax (strict > keeps lowest index on ties, like jnp.argmax)
    float4 cs[8] = {c0, c1, c2, c3, c4, c5, c6, c7};
    float bx = cs[0].x, by = cs[0].y, bz = cs[0].z, bw = cs[0].w;
    int ix = 0, iy = 0, iz = 0, iw = 0;
#pragma unroll
    for (int k = 1; k < 8; k++) {
        if (cs[k].x > bx) { bx = cs[k].x; ix = k; }
        if (cs[k].y > by) { by = cs[k].y; iy = k; }
        if (cs[k].z > bz) { bz = cs[k].z; iz = k; }
        if (cs[k].w > bw) { bw = cs[k].w; iw = k; }
    }

    float mx = sqrtf(g0.x * g0.x + g1.x * g1.x);
    float my = sqrtf(g0.y * g0.y + g1.y * g1.y);
    float mz = sqrtf(g0.z * g0.z + g1.z * g1.z);
    float mw = sqrtf(g0.w * g0.w + g1.w * g1.w);

    float4* out_base = out + (size_t)b * 8 * VPB + p;
#pragma unroll
    for (int k = 0; k < 8; k++) {
        float4 o;
        o.x = (ix == k) ? mx : 0.0f;
        o.y = (iy == k) ? my : 0.0f;
        o.z = (iz == k) ? mz : 0.0f;
        o.w = (iw == k) ? mw : 0.0f;
        __stwt(&out_base[(size_t)k * VPB], o);  // write-through to DRAM
    }
}

extern "C" void kernel_launch(void* const* d_in, const int* in_sizes, int n_in,
                              void* d_out, int out_size)
{
    const float4* x = (const float4*)d_in[0];
    float4* out = (float4*)d_out;
    histogram_layer_kernel<<<TOTAL_VEC / 256, 256>>>(x, out);
}

// round 7
// speedup vs baseline: 1.0267x; 1.0033x over previous
#include <cuda_runtime.h>
#include <math.h>

// x: (16, 10, 512, 512) f32. out: (16, 8, 512, 512) f32.
// Per pixel: mag = sqrt(x[8]^2 + x[9]^2); k = argmax over x[0..7] (first max);
// out[c] = (c==k) ? mag : 0.
//
// One thread per float4. Channel stride = 65536 float4s; all accesses 16B
// coalesced. Stores are write-through (__stwt): no L2 dirty accumulation,
// writes stream to DRAM in issue order as full-sector bursts.

#define VPB 65536            // float4 vectors per channel (512*512/4)
#define NBATCH 16
#define TOTAL_VEC (NBATCH * VPB)   // 1,048,576 threads exactly

__global__ __launch_bounds__(256, 4) void histogram_layer_kernel(
    const float4* __restrict__ x, float4* __restrict__ out)
{
    int i = blockIdx.x * blockDim.x + threadIdx.x;  // grid exact, no guard

    int b = i >> 16;          // i / VPB
    int p = i & (VPB - 1);    // i % VPB

    const float4* in_base = x + (size_t)b * 10 * VPB + p;

    // Front-batch ALL ten loads into live registers before any consumption.
    float4 c0 = in_base[(size_t)0 * VPB];
    float4 c1 = in_base[(size_t)1 * VPB];
    float4 c2 = in_base[(size_t)2 * VPB];
    float4 c3 = in_base[(size_t)3 * VPB];
    float4 c4 = in_base[(size_t)4 * VPB];
    float4 c5 = in_base[(size_t)5 * VPB];
    float4 c6 = in_base[(size_t)6 * VPB];
    float4 c7 = in_base[(size_t)7 * VPB];
    float4 g0 = in_base[(size_t)8 * VPB];
    float4 g1 = in_base[(size_t)9 * VPB];

    // Per-lane argmax (strict > keeps lowest index on ties, like jnp.argmax)
    float4 cs[8] = {c0, c1, c2, c3, c4, c5, c6, c7};
    float bx = cs[0].x, by = cs[0].y, bz = cs[0].z, bw = cs[0].w;
    int ix = 0, iy = 0, iz = 0, iw = 0;
#pragma unroll
    for (int k = 1; k < 8; k++) {
        if (cs[k].x > bx) { bx = cs[k].x; ix = k; }
        if (cs[k].y > by) { by = cs[k].y; iy = k; }
        if (cs[k].z > bz) { bz = cs[k].z; iz = k; }
        if (cs[k].w > bw) { bw = cs[k].w; iw = k; }
    }

    float mx = sqrtf(g0.x * g0.x + g1.x * g1.x);
    float my = sqrtf(g0.y * g0.y + g1.y * g1.y);
    float mz = sqrtf(g0.z * g0.z + g1.z * g1.z);
    float mw = sqrtf(g0.w * g0.w + g1.w * g1.w);

    float4* out_base = out + (size_t)b * 8 * VPB + p;
#pragma unroll
    for (int k = 0; k < 8; k++) {
        float4 o;
        o.x = (ix == k) ? mx : 0.0f;
        o.y = (iy == k) ? my : 0.0f;
        o.z = (iz == k) ? mz : 0.0f;
        o.w = (iw == k) ? mw : 0.0f;
        __stwt(&out_base[(size_t)k * VPB], o);  // write-through to DRAM
    }
}

extern "C" void kernel_launch(void* const* d_in, const int* in_sizes, int n_in,
                              void* d_out, int out_size)
{
    const float4* x = (const float4*)d_in[0];
    float4* out = (float4*)d_out;
    histogram_layer_kernel<<<TOTAL_VEC / 256, 256>>>(x, out);
}